// round 1
// baseline (speedup 1.0000x reference)
#include <cuda_runtime.h>
#include <cstddef>

#define B_  2
#define S_  4096
#define D_  512
#define H_  8
#define DK_ 64
#define NQT (S_/64)

// Scratch for attention output before the W_o projection (alloc-free rule).
__device__ float g_attn[(size_t)B_ * S_ * D_];

// ---------------------------------------------------------------------------
// Flash attention: one block = one (b, h) pair and one 64-row query tile.
// 64 threads, each owns an 8x8 register tile of the 64x64 score/output tiles.
// Shared memory = 48KB exactly: Qs + KPs (K, later reused for P) + Vs.
// KPs is rotate-swizzled to kill bank conflicts with stride-64 rows.
// ---------------------------------------------------------------------------
__global__ __launch_bounds__(64, 4)
void attn_kernel(const float* __restrict__ Q,
                 const float* __restrict__ K,
                 const float* __restrict__ V)
{
    __shared__ float Qs[64][64];
    __shared__ float KPs[64][64];
    __shared__ float Vs[64][64];

    const int qt  = blockIdx.x;       // query tile 0..63
    const int bh  = blockIdx.y;       // 0..15
    const int b   = bh >> 3;
    const int h   = bh & 7;
    const int tid = threadIdx.x;
    const int ty  = tid >> 3;         // 0..7 -> q rows ty*8 .. ty*8+7
    const int tx  = tid & 7;          // 0..7 -> cols  tx*8 .. tx*8+7

    const float* qbase = Q + ((size_t)(b * S_ + qt * 64)) * D_ + h * DK_;
    const float* kbase = K + ((size_t)b * S_) * D_ + h * DK_;
    const float* vbase = V + ((size_t)b * S_) * D_ + h * DK_;

    // Load Q tile, pre-scaled by 1/sqrt(DK) = 0.125
    for (int i = tid; i < 64 * 16; i += 64) {
        int r = i >> 4, c = (i & 15) << 2;
        float4 t = *(const float4*)(qbase + (size_t)r * D_ + c);
        Qs[r][c + 0] = t.x * 0.125f;
        Qs[r][c + 1] = t.y * 0.125f;
        Qs[r][c + 2] = t.z * 0.125f;
        Qs[r][c + 3] = t.w * 0.125f;
    }

    float o[8][8];
    float m[8], l[8];
#pragma unroll
    for (int i = 0; i < 8; i++) {
        m[i] = -1e30f;
        l[i] = 0.f;
#pragma unroll
        for (int j = 0; j < 8; j++) o[i][j] = 0.f;
    }

    for (int kt = 0; kt < S_ / 64; kt++) {
        // Load K tile (rotate swizzle: col' = (col + row) & 63) and V tile.
        for (int i = tid; i < 64 * 16; i += 64) {
            int r = i >> 4, c = (i & 15) << 2;
            float4 t = *(const float4*)(kbase + (size_t)(kt * 64 + r) * D_ + c);
            KPs[r][(c + 0 + r) & 63] = t.x;
            KPs[r][(c + 1 + r) & 63] = t.y;
            KPs[r][(c + 2 + r) & 63] = t.z;
            KPs[r][(c + 3 + r) & 63] = t.w;
            float4 u = *(const float4*)(vbase + (size_t)(kt * 64 + r) * D_ + c);
            *(float4*)&Vs[r][c] = u;
        }
        __syncthreads();

        // S = (Q * scale) K^T  -- 8x8 per thread
        float s[8][8];
#pragma unroll
        for (int i = 0; i < 8; i++)
#pragma unroll
            for (int j = 0; j < 8; j++) s[i][j] = 0.f;

#pragma unroll 4
        for (int d = 0; d < 64; d++) {
            float qr[8], kr[8];
#pragma unroll
            for (int i = 0; i < 8; i++) qr[i] = Qs[ty * 8 + i][d];
#pragma unroll
            for (int j = 0; j < 8; j++) {
                int row = tx * 8 + j;
                kr[j] = KPs[row][(d + row) & 63];
            }
#pragma unroll
            for (int i = 0; i < 8; i++)
#pragma unroll
                for (int j = 0; j < 8; j++)
                    s[i][j] += qr[i] * kr[j];
        }

        // Online softmax (rows split across the 8-lane tx group).
#pragma unroll
        for (int i = 0; i < 8; i++) {
            float rm = s[i][0];
#pragma unroll
            for (int j = 1; j < 8; j++) rm = fmaxf(rm, s[i][j]);
            rm = fmaxf(rm, __shfl_xor_sync(0xffffffffu, rm, 1));
            rm = fmaxf(rm, __shfl_xor_sync(0xffffffffu, rm, 2));
            rm = fmaxf(rm, __shfl_xor_sync(0xffffffffu, rm, 4));
            float mn   = fmaxf(m[i], rm);
            float corr = __expf(m[i] - mn);
            float rs = 0.f;
#pragma unroll
            for (int j = 0; j < 8; j++) {
                float p = __expf(s[i][j] - mn);
                s[i][j] = p;
                rs += p;
            }
            rs += __shfl_xor_sync(0xffffffffu, rs, 1);
            rs += __shfl_xor_sync(0xffffffffu, rs, 2);
            rs += __shfl_xor_sync(0xffffffffu, rs, 4);
            l[i] = l[i] * corr + rs;
            m[i] = mn;
#pragma unroll
            for (int c = 0; c < 8; c++) o[i][c] *= corr;
        }
        __syncthreads();   // all K reads done before P overwrites KPs

        // Store P into KPs (swizzle: col' = (col + (row>>3)) & 63 ; row>>3 == ty)
#pragma unroll
        for (int i = 0; i < 8; i++)
#pragma unroll
            for (int j = 0; j < 8; j++)
                KPs[ty * 8 + i][(tx * 8 + j + ty) & 63] = s[i][j];
        __syncthreads();

        // O += P V
#pragma unroll 4
        for (int kk = 0; kk < 64; kk++) {
            float pr[8];
#pragma unroll
            for (int i = 0; i < 8; i++)
                pr[i] = KPs[ty * 8 + i][(kk + ty) & 63];
            float4 v0 = *(const float4*)&Vs[kk][tx * 8];
            float4 v1 = *(const float4*)&Vs[kk][tx * 8 + 4];
            float vr[8] = {v0.x, v0.y, v0.z, v0.w, v1.x, v1.y, v1.z, v1.w};
#pragma unroll
            for (int i = 0; i < 8; i++)
#pragma unroll
                for (int c = 0; c < 8; c++)
                    o[i][c] += pr[i] * vr[c];
        }
        __syncthreads();   // before next tile's loads overwrite KPs/Vs
    }

    // Normalize and write attention output to scratch.
    float* obase = g_attn + ((size_t)(b * S_ + qt * 64 + ty * 8)) * D_
                 + h * DK_ + tx * 8;
#pragma unroll
    for (int i = 0; i < 8; i++) {
        float inv = 1.f / l[i];
        float4 r0, r1;
        r0.x = o[i][0] * inv; r0.y = o[i][1] * inv;
        r0.z = o[i][2] * inv; r0.w = o[i][3] * inv;
        r1.x = o[i][4] * inv; r1.y = o[i][5] * inv;
        r1.z = o[i][6] * inv; r1.w = o[i][7] * inv;
        *(float4*)(obase + (size_t)i * D_)     = r0;
        *(float4*)(obase + (size_t)i * D_ + 4) = r1;
    }
}

// ---------------------------------------------------------------------------
// Projection: out[8192,512] = g_attn[8192,512] @ W[512,512] + b
// 64x64 block tile, 64 threads, 8x8 per thread, k-tiles of 32.
// ---------------------------------------------------------------------------
__global__ __launch_bounds__(64, 8)
void proj_kernel(const float* __restrict__ W,
                 const float* __restrict__ bias,
                 float* __restrict__ out)
{
    __shared__ float As[64][33];
    __shared__ float Ws[32][64];

    const int nb  = blockIdx.x;   // n tile: 0..7
    const int mb  = blockIdx.y;   // m tile: 0..127
    const int tid = threadIdx.x;
    const int ty  = tid >> 3;
    const int tx  = tid & 7;

    float acc[8][8];
#pragma unroll
    for (int i = 0; i < 8; i++)
#pragma unroll
        for (int j = 0; j < 8; j++) acc[i][j] = 0.f;

    const float* abase = g_attn + (size_t)mb * 64 * D_;

    for (int k0 = 0; k0 < D_; k0 += 32) {
        for (int i = tid; i < 64 * 8; i += 64) {
            int r = i >> 3, c = (i & 7) << 2;
            float4 t = *(const float4*)(abase + (size_t)r * D_ + k0 + c);
            As[r][c + 0] = t.x; As[r][c + 1] = t.y;
            As[r][c + 2] = t.z; As[r][c + 3] = t.w;
        }
        for (int i = tid; i < 32 * 16; i += 64) {
            int r = i >> 4, c = (i & 15) << 2;
            float4 t = *(const float4*)(W + (size_t)(k0 + r) * D_ + nb * 64 + c);
            *(float4*)&Ws[r][c] = t;
        }
        __syncthreads();

#pragma unroll 4
        for (int kk = 0; kk < 32; kk++) {
            float a[8];
#pragma unroll
            for (int i = 0; i < 8; i++) a[i] = As[ty * 8 + i][kk];
            float4 w0 = *(const float4*)&Ws[kk][tx * 8];
            float4 w1 = *(const float4*)&Ws[kk][tx * 8 + 4];
            float w[8] = {w0.x, w0.y, w0.z, w0.w, w1.x, w1.y, w1.z, w1.w};
#pragma unroll
            for (int i = 0; i < 8; i++)
#pragma unroll
                for (int c = 0; c < 8; c++)
                    acc[i][c] += a[i] * w[c];
        }
        __syncthreads();
    }

    float4 bv0 = *(const float4*)(bias + nb * 64 + tx * 8);
    float4 bv1 = *(const float4*)(bias + nb * 64 + tx * 8 + 4);
    float bv[8] = {bv0.x, bv0.y, bv0.z, bv0.w, bv1.x, bv1.y, bv1.z, bv1.w};

#pragma unroll
    for (int i = 0; i < 8; i++) {
        float4 r0, r1;
        r0.x = acc[i][0] + bv[0]; r0.y = acc[i][1] + bv[1];
        r0.z = acc[i][2] + bv[2]; r0.w = acc[i][3] + bv[3];
        r1.x = acc[i][4] + bv[4]; r1.y = acc[i][5] + bv[5];
        r1.z = acc[i][6] + bv[6]; r1.w = acc[i][7] + bv[7];
        float* po = out + (size_t)(mb * 64 + ty * 8 + i) * D_ + nb * 64 + tx * 8;
        *(float4*)(po)     = r0;
        *(float4*)(po + 4) = r1;
    }
}

extern "C" void kernel_launch(void* const* d_in, const int* in_sizes, int n_in,
                              void* d_out, int out_size)
{
    (void)in_sizes; (void)n_in; (void)out_size;
    const float* Q    = (const float*)d_in[0];
    const float* K    = (const float*)d_in[1];
    const float* V    = (const float*)d_in[2];
    const float* W    = (const float*)d_in[3];
    const float* bias = (const float*)d_in[4];
    float* out = (float*)d_out;

    attn_kernel<<<dim3(NQT, B_ * H_), 64>>>(Q, K, V);
    proj_kernel<<<dim3(D_ / 64, (B_ * S_) / 64), 64>>>(W, bias, out);
}

// round 3
// speedup vs baseline: 3.4893x; 3.4893x over previous
#include <cuda_runtime.h>
#include <cstdint>
#include <cstddef>

#define B_  2
#define S_  4096
#define D_  512
#define H_  8
#define DK_ 64

// Scratch for pre-projection attention output (alloc-free rule).
__device__ float g_attn[(size_t)B_ * S_ * D_];

__device__ __forceinline__ float to_tf32(float x) {
    float r;
    asm("cvt.rna.tf32.f32 %0, %1;" : "=f"(r) : "f"(x));
    return r;
}

// D = A*B + D, tf32 m16n8k8 (legal on base sm_103 target; runs on tensor pipe).
__device__ __forceinline__ void mma_tf32(float c[4], const uint32_t a[4],
                                         uint32_t b0, uint32_t b1) {
    asm volatile(
        "mma.sync.aligned.m16n8k8.row.col.f32.tf32.tf32.f32 "
        "{%0,%1,%2,%3}, {%4,%5,%6,%7}, {%8,%9}, {%0,%1,%2,%3};"
        : "+f"(c[0]), "+f"(c[1]), "+f"(c[2]), "+f"(c[3])
        : "r"(a[0]), "r"(a[1]), "r"(a[2]), "r"(a[3]), "r"(b0), "r"(b1));
}

// Shared-memory strides (floats). Chosen so fragment LDS patterns are
// conflict-free: K/P stride 68 -> bank = (4g+t) all distinct;
// V stride 72 -> bank = (8t+g) all distinct.
#define KS_STRIDE 68
#define VS_STRIDE 72
#define PS_STRIDE 68
#define SMEM_FLOATS (64 * KS_STRIDE + 64 * VS_STRIDE + 128 * PS_STRIDE)

#define NKT (S_ / 64)

// ---------------------------------------------------------------------------
// tf32 warp-MMA flash attention (no-max softmax, O resident in registers).
// CTA = (b, h, 128-query tile). 4 warps; warp owns 32 query rows (2 m-tiles).
// ---------------------------------------------------------------------------
__global__ __launch_bounds__(128, 2)
void attn_kernel(const float* __restrict__ Q,
                 const float* __restrict__ K,
                 const float* __restrict__ V)
{
    extern __shared__ float smem[];
    float* Ks = smem;                                   // [64][68]
    float* Vs = smem + 64 * KS_STRIDE;                  // [64][72]
    float* Ps = smem + 64 * KS_STRIDE + 64 * VS_STRIDE; // [128][68]

    const int tid  = threadIdx.x;
    const int warp = tid >> 5;
    const int lane = tid & 31;
    const int g    = lane >> 2;   // groupID: row within m8 block / col for B
    const int t    = lane & 3;    // threadID in group
    const int qt   = blockIdx.x;  // 0..31
    const int bh   = blockIdx.y;  // 0..15
    const int b    = bh >> 3, h = bh & 7;

    // ---- stage Q tile into Ps (scaled 1/8, tf32-rounded), then to frags ----
    const float* qb = Q + ((size_t)(b * S_ + qt * 128)) * D_ + h * DK_;
    for (int i = tid; i < 128 * 16; i += 128) {
        int r = i >> 4, c = (i & 15) << 2;
        float4 x = *(const float4*)(qb + (size_t)r * D_ + c);
        x.x = to_tf32(x.x * 0.125f);
        x.y = to_tf32(x.y * 0.125f);
        x.z = to_tf32(x.z * 0.125f);
        x.w = to_tf32(x.w * 0.125f);
        *(float4*)(Ps + r * PS_STRIDE + c) = x;
    }
    __syncthreads();

    uint32_t qa[2][8][4];   // Q A-fragments, resident all kernel
#pragma unroll
    for (int mt = 0; mt < 2; mt++) {
        const int r0 = warp * 32 + mt * 16 + g;
#pragma unroll
        for (int ks = 0; ks < 8; ks++) {
            const int c0 = ks * 8 + t;
            qa[mt][ks][0] = __float_as_uint(Ps[(r0    ) * PS_STRIDE + c0    ]);
            qa[mt][ks][1] = __float_as_uint(Ps[(r0 + 8) * PS_STRIDE + c0    ]);
            qa[mt][ks][2] = __float_as_uint(Ps[(r0    ) * PS_STRIDE + c0 + 4]);
            qa[mt][ks][3] = __float_as_uint(Ps[(r0 + 8) * PS_STRIDE + c0 + 4]);
        }
    }
    // (first __syncthreads in the loop orders extraction before any P store)

    float o[2][8][4];
    float l[2][2];
#pragma unroll
    for (int mt = 0; mt < 2; mt++) {
        l[mt][0] = 0.f; l[mt][1] = 0.f;
#pragma unroll
        for (int nt = 0; nt < 8; nt++)
#pragma unroll
            for (int j = 0; j < 4; j++) o[mt][nt][j] = 0.f;
    }

    const float* kb0 = K + ((size_t)b * S_) * D_ + h * DK_;
    const float* vb0 = V + ((size_t)b * S_) * D_ + h * DK_;

    for (int kt = 0; kt < NKT; kt++) {
        // ---- load K tile (tf32) + V tile (tf32) ----
        const float* kb = kb0 + (size_t)(kt * 64) * D_;
        const float* vb = vb0 + (size_t)(kt * 64) * D_;
        for (int i = tid; i < 64 * 16; i += 128) {
            int r = i >> 4, c = (i & 15) << 2;
            float4 x = *(const float4*)(kb + (size_t)r * D_ + c);
            x.x = to_tf32(x.x); x.y = to_tf32(x.y);
            x.z = to_tf32(x.z); x.w = to_tf32(x.w);
            *(float4*)(Ks + r * KS_STRIDE + c) = x;
            float4 y = *(const float4*)(vb + (size_t)r * D_ + c);
            y.x = to_tf32(y.x); y.y = to_tf32(y.y);
            y.z = to_tf32(y.z); y.w = to_tf32(y.w);
            *(float4*)(Vs + r * VS_STRIDE + c) = y;
        }
        __syncthreads();

        // ---- MMA1 (S = Q K^T) + exp + P store, per 8-col n-tile ----
#pragma unroll
        for (int nt = 0; nt < 8; nt++) {
            float c4[2][4];
#pragma unroll
            for (int mt = 0; mt < 2; mt++)
#pragma unroll
                for (int j = 0; j < 4; j++) c4[mt][j] = 0.f;

#pragma unroll
            for (int ks = 0; ks < 8; ks++) {
                // B-frag: B[k][n] = K[key = nt*8+g][dk = ks*8+t(+4)]
                const float* kr = Ks + (nt * 8 + g) * KS_STRIDE + ks * 8 + t;
                uint32_t b0v = __float_as_uint(kr[0]);
                uint32_t b1v = __float_as_uint(kr[4]);
                mma_tf32(c4[0], qa[0][ks], b0v, b1v);
                mma_tf32(c4[1], qa[1][ks], b0v, b1v);
            }
#pragma unroll
            for (int mt = 0; mt < 2; mt++) {
                float e0 = __expf(c4[mt][0]);
                float e1 = __expf(c4[mt][1]);
                float e2 = __expf(c4[mt][2]);
                float e3 = __expf(c4[mt][3]);
                l[mt][0] += e0 + e1;
                l[mt][1] += e2 + e3;
                const int r0  = warp * 32 + mt * 16 + g;
                const int col = nt * 8 + 2 * t;
                float2 p0 = make_float2(to_tf32(e0), to_tf32(e1));
                float2 p1 = make_float2(to_tf32(e2), to_tf32(e3));
                *(float2*)(Ps + (r0    ) * PS_STRIDE + col) = p0;
                *(float2*)(Ps + (r0 + 8) * PS_STRIDE + col) = p1;
            }
        }
        __syncwarp();   // warp reads back only its own P rows

        // ---- MMA2: O += P V  (ks outer so P A-frags load once) ----
#pragma unroll
        for (int ks = 0; ks < 8; ks++) {
            uint32_t pa[2][4];
#pragma unroll
            for (int mt = 0; mt < 2; mt++) {
                const int r0 = warp * 32 + mt * 16 + g;
                const int c0 = ks * 8 + t;
                pa[mt][0] = __float_as_uint(Ps[(r0    ) * PS_STRIDE + c0    ]);
                pa[mt][1] = __float_as_uint(Ps[(r0 + 8) * PS_STRIDE + c0    ]);
                pa[mt][2] = __float_as_uint(Ps[(r0    ) * PS_STRIDE + c0 + 4]);
                pa[mt][3] = __float_as_uint(Ps[(r0 + 8) * PS_STRIDE + c0 + 4]);
            }
#pragma unroll
            for (int nt = 0; nt < 8; nt++) {
                // B-frag: B[k][n] = V[key = ks*8+t(+4)][dk = nt*8+g]
                uint32_t b0v = __float_as_uint(Vs[(ks * 8 + t    ) * VS_STRIDE + nt * 8 + g]);
                uint32_t b1v = __float_as_uint(Vs[(ks * 8 + t + 4) * VS_STRIDE + nt * 8 + g]);
                mma_tf32(o[0][nt], pa[0], b0v, b1v);
                mma_tf32(o[1][nt], pa[1], b0v, b1v);
            }
        }
        __syncthreads();   // before next tile's loads overwrite Ks/Vs
    }

    // ---- final row-sum reduce (quad) + normalize + store ----
    float inv[2][2];
#pragma unroll
    for (int mt = 0; mt < 2; mt++)
#pragma unroll
        for (int r = 0; r < 2; r++) {
            float v = l[mt][r];
            v += __shfl_xor_sync(0xffffffffu, v, 1);
            v += __shfl_xor_sync(0xffffffffu, v, 2);
            inv[mt][r] = 1.f / v;
        }

#pragma unroll
    for (int mt = 0; mt < 2; mt++) {
        const int row0 = qt * 128 + warp * 32 + mt * 16 + g;
        float* ob = g_attn + ((size_t)(b * S_ + row0)) * D_ + h * DK_;
#pragma unroll
        for (int nt = 0; nt < 8; nt++) {
            const int col = nt * 8 + 2 * t;
            float2 r0 = make_float2(o[mt][nt][0] * inv[mt][0],
                                    o[mt][nt][1] * inv[mt][0]);
            float2 r1 = make_float2(o[mt][nt][2] * inv[mt][1],
                                    o[mt][nt][3] * inv[mt][1]);
            *(float2*)(ob + col)            = r0;
            *(float2*)(ob + 8 * D_ + col)   = r1;
        }
    }
}

// ---------------------------------------------------------------------------
// Projection: out[8192,512] = g_attn @ W + b  (exact fp32 SIMT)
// ---------------------------------------------------------------------------
__global__ __launch_bounds__(64, 8)
void proj_kernel(const float* __restrict__ W,
                 const float* __restrict__ bias,
                 float* __restrict__ out)
{
    __shared__ float As[64][33];
    __shared__ float Ws[32][64];

    const int nb  = blockIdx.x;
    const int mb  = blockIdx.y;
    const int tid = threadIdx.x;
    const int ty  = tid >> 3;
    const int tx  = tid & 7;

    float acc[8][8];
#pragma unroll
    for (int i = 0; i < 8; i++)
#pragma unroll
        for (int j = 0; j < 8; j++) acc[i][j] = 0.f;

    const float* abase = g_attn + (size_t)mb * 64 * D_;

    for (int k0 = 0; k0 < D_; k0 += 32) {
        for (int i = tid; i < 64 * 8; i += 64) {
            int r = i >> 3, c = (i & 7) << 2;
            float4 x = *(const float4*)(abase + (size_t)r * D_ + k0 + c);
            As[r][c + 0] = x.x; As[r][c + 1] = x.y;
            As[r][c + 2] = x.z; As[r][c + 3] = x.w;
        }
        for (int i = tid; i < 32 * 16; i += 64) {
            int r = i >> 4, c = (i & 15) << 2;
            float4 x = *(const float4*)(W + (size_t)(k0 + r) * D_ + nb * 64 + c);
            *(float4*)&Ws[r][c] = x;
        }
        __syncthreads();

#pragma unroll 4
        for (int kk = 0; kk < 32; kk++) {
            float a[8];
#pragma unroll
            for (int i = 0; i < 8; i++) a[i] = As[ty * 8 + i][kk];
            float4 w0 = *(const float4*)&Ws[kk][tx * 8];
            float4 w1 = *(const float4*)&Ws[kk][tx * 8 + 4];
            float w[8] = {w0.x, w0.y, w0.z, w0.w, w1.x, w1.y, w1.z, w1.w};
#pragma unroll
            for (int i = 0; i < 8; i++)
#pragma unroll
                for (int c = 0; c < 8; c++)
                    acc[i][c] += a[i] * w[c];
        }
        __syncthreads();
    }

    float4 bv0 = *(const float4*)(bias + nb * 64 + tx * 8);
    float4 bv1 = *(const float4*)(bias + nb * 64 + tx * 8 + 4);
    float bv[8] = {bv0.x, bv0.y, bv0.z, bv0.w, bv1.x, bv1.y, bv1.z, bv1.w};

#pragma unroll
    for (int i = 0; i < 8; i++) {
        float4 r0, r1;
        r0.x = acc[i][0] + bv[0]; r0.y = acc[i][1] + bv[1];
        r0.z = acc[i][2] + bv[2]; r0.w = acc[i][3] + bv[3];
        r1.x = acc[i][4] + bv[4]; r1.y = acc[i][5] + bv[5];
        r1.z = acc[i][6] + bv[6]; r1.w = acc[i][7] + bv[7];
        float* po = out + (size_t)(mb * 64 + ty * 8 + i) * D_ + nb * 64 + tx * 8;
        *(float4*)(po)     = r0;
        *(float4*)(po + 4) = r1;
    }
}

extern "C" void kernel_launch(void* const* d_in, const int* in_sizes, int n_in,
                              void* d_out, int out_size)
{
    (void)in_sizes; (void)n_in; (void)out_size;
    const float* Q    = (const float*)d_in[0];
    const float* K    = (const float*)d_in[1];
    const float* V    = (const float*)d_in[2];
    const float* W    = (const float*)d_in[3];
    const float* bias = (const float*)d_in[4];
    float* out = (float*)d_out;

    const int smem_bytes = SMEM_FLOATS * sizeof(float);
    cudaFuncSetAttribute(attn_kernel, cudaFuncAttributeMaxDynamicSharedMemorySize,
                         smem_bytes);

    attn_kernel<<<dim3(S_ / 128, B_ * H_), 128, smem_bytes>>>(Q, K, V);
    proj_kernel<<<dim3(D_ / 64, (B_ * S_) / 64), 64>>>(W, bias, out);
}